// round 1
// baseline (speedup 1.0000x reference)
#include <cuda_runtime.h>
#include <math.h>

// Problem constants
#define B_  4
#define N_  10000
#define E_  100000
#define H_  8
#define FIN_ 256   // H*F = 8*32

// -------------------- scratch (device globals, no allocation) --------------
__device__ float    g_proj  [B_ * N_ * FIN_];   // x @ W^T
__device__ float    g_numer [B_ * N_ * FIN_];   // segsum(proj[src]*att)
__device__ float    g_relagg[B_ * N_ * FIN_];   // segsum(rel)
__device__ float    g_se    [B_ * E_ * H_  ];   // edge scores / exp scores
__device__ float    g_ssrc  [B_ * N_ * H_  ];
__device__ float    g_strg  [B_ * N_ * H_  ];
__device__ float    g_denom [B_ * N_ * H_  ];
__device__ unsigned g_maxu  [B_];               // ordered-uint encoded max

// -------------------- helpers ---------------------------------------------
__device__ __forceinline__ unsigned f2o(float f) {
    unsigned u = __float_as_uint(f);
    return (u & 0x80000000u) ? ~u : (u ^ 0x80000000u);
}
__device__ __forceinline__ float o2f(unsigned u) {
    return (u & 0x80000000u) ? __uint_as_float(u ^ 0x80000000u)
                             : __uint_as_float(~u);
}
__device__ __forceinline__ void red_add_v4(float* addr, float4 v) {
    asm volatile("red.global.add.v4.f32 [%0], {%1,%2,%3,%4};"
                 :: "l"(addr), "f"(v.x), "f"(v.y), "f"(v.z), "f"(v.w)
                 : "memory");
}

// -------------------- K0: zero scratch -------------------------------------
__global__ void zero_kernel() {
    int i = blockIdx.x * blockDim.x + threadIdx.x;
    int stride = gridDim.x * blockDim.x;
    float4 z = make_float4(0.f, 0.f, 0.f, 0.f);
    float4* n4 = reinterpret_cast<float4*>(g_numer);
    float4* r4 = reinterpret_cast<float4*>(g_relagg);
    const int NV = (B_ * N_ * FIN_) / 4;  // 2,560,000
    for (int j = i; j < NV; j += stride) { n4[j] = z; r4[j] = z; }
    const int ND = B_ * N_ * H_;          // 320,000
    for (int j = i; j < ND; j += stride) g_denom[j] = 0.f;
    if (i < B_) g_maxu[i] = 0u;           // encodes below any real value
}

// -------------------- K1: proj = x @ W^T  (writes g_proj) ------------------
// Tiles: BM=64, BN=64, BK=16, 256 threads, 4x4 microtile per thread.
__global__ void gemm0_kernel(const float* __restrict__ A,
                             const float* __restrict__ W) {
    __shared__ float As[16][68];
    __shared__ float Bs[16][68];
    const int t  = threadIdx.x;
    const int bm = blockIdx.y * 64;
    const int bn = blockIdx.x * 64;
    const int tx = t & 15, ty = t >> 4;
    const int arow = t >> 2;          // 0..63
    const int kq   = (t & 3) * 4;     // 0,4,8,12
    const float* Ap = A + (bm + arow) * FIN_;
    const float* Wp = W + (bn + arow) * FIN_;
    float acc[4][4] = {};
    for (int k0 = 0; k0 < FIN_; k0 += 16) {
        float4 av = *reinterpret_cast<const float4*>(Ap + k0 + kq);
        float4 bv = *reinterpret_cast<const float4*>(Wp + k0 + kq);
        As[kq+0][arow] = av.x; As[kq+1][arow] = av.y;
        As[kq+2][arow] = av.z; As[kq+3][arow] = av.w;
        Bs[kq+0][arow] = bv.x; Bs[kq+1][arow] = bv.y;
        Bs[kq+2][arow] = bv.z; Bs[kq+3][arow] = bv.w;
        __syncthreads();
        #pragma unroll
        for (int k = 0; k < 16; k++) {
            float4 ar = *reinterpret_cast<const float4*>(&As[k][ty * 4]);
            float4 br = *reinterpret_cast<const float4*>(&Bs[k][tx * 4]);
            acc[0][0] += ar.x * br.x; acc[0][1] += ar.x * br.y;
            acc[0][2] += ar.x * br.z; acc[0][3] += ar.x * br.w;
            acc[1][0] += ar.y * br.x; acc[1][1] += ar.y * br.y;
            acc[1][2] += ar.y * br.z; acc[1][3] += ar.y * br.w;
            acc[2][0] += ar.z * br.x; acc[2][1] += ar.z * br.y;
            acc[2][2] += ar.z * br.z; acc[2][3] += ar.z * br.w;
            acc[3][0] += ar.w * br.x; acc[3][1] += ar.w * br.y;
            acc[3][2] += ar.w * br.z; acc[3][3] += ar.w * br.w;
        }
        __syncthreads();
    }
    #pragma unroll
    for (int i = 0; i < 4; i++) {
        int row = bm + ty * 4 + i;
        float4 v = make_float4(acc[i][0], acc[i][1], acc[i][2], acc[i][3]);
        *reinterpret_cast<float4*>(g_proj + row * FIN_ + bn + tx * 4) = v;
    }
}

// -------------------- K2: s_src / s_trg ------------------------------------
__global__ void s_kernel(const float* __restrict__ a_src,
                         const float* __restrict__ a_trg) {
    int idx = blockIdx.x * blockDim.x + threadIdx.x;  // (b*N+n)*H + h
    if (idx >= B_ * N_ * H_) return;
    int h   = idx & 7;
    int row = idx >> 3;
    const float4* p  = reinterpret_cast<const float4*>(g_proj + row * FIN_ + h * 32);
    const float4* a1 = reinterpret_cast<const float4*>(a_src + h * 32);
    const float4* a2 = reinterpret_cast<const float4*>(a_trg + h * 32);
    float s1 = 0.f, s2 = 0.f;
    #pragma unroll
    for (int j = 0; j < 8; j++) {
        float4 pv = p[j], v1 = a1[j], v2 = a2[j];
        s1 += pv.x * v1.x + pv.y * v1.y + pv.z * v1.z + pv.w * v1.w;
        s2 += pv.x * v2.x + pv.y * v2.y + pv.z * v2.z + pv.w * v2.w;
    }
    g_ssrc[idx] = s1;
    g_strg[idx] = s2;
}

// -------------------- K3: per-edge leaky-relu score + batch max ------------
__global__ void edge_score_kernel(const int* __restrict__ EI) {
    const int b = blockIdx.y;
    const int e = blockIdx.x * 256 + threadIdx.x;
    float lmax = -INFINITY;
    if (e < E_) {
        int src = EI[b * 2 * E_ + e];
        int trg = EI[b * 2 * E_ + E_ + e];
        const float* s1 = g_ssrc + (b * N_ + src) * H_;
        const float* s2 = g_strg + (b * N_ + trg) * H_;
        float v[8];
        #pragma unroll
        for (int h = 0; h < 8; h++) {
            float s = s1[h] + s2[h];
            s = (s > 0.f) ? s : 0.2f * s;
            v[h] = s;
            lmax = fmaxf(lmax, s);
        }
        float4* sp = reinterpret_cast<float4*>(g_se + (size_t)(b * E_ + e) * H_);
        sp[0] = make_float4(v[0], v[1], v[2], v[3]);
        sp[1] = make_float4(v[4], v[5], v[6], v[7]);
    }
    // block-wide max reduction
    #pragma unroll
    for (int o = 16; o; o >>= 1)
        lmax = fmaxf(lmax, __shfl_xor_sync(0xFFFFFFFFu, lmax, o));
    __shared__ float wmax[8];
    int lane = threadIdx.x & 31, wid = threadIdx.x >> 5;
    if (lane == 0) wmax[wid] = lmax;
    __syncthreads();
    if (threadIdx.x == 0) {
        float m = wmax[0];
        #pragma unroll
        for (int w = 1; w < 8; w++) m = fmaxf(m, wmax[w]);
        atomicMax(&g_maxu[b], f2o(m));
    }
}

// -------------------- K4: exp(s - max) + denom scatter ---------------------
__global__ void exp_denom_kernel(const int* __restrict__ EI) {
    const int b = blockIdx.y;
    const int e = blockIdx.x * 256 + threadIdx.x;
    if (e >= E_) return;
    const float mx = o2f(g_maxu[b]);
    float4* sp = reinterpret_cast<float4*>(g_se + (size_t)(b * E_ + e) * H_);
    float4 v0 = sp[0], v1 = sp[1];
    v0.x = expf(v0.x - mx); v0.y = expf(v0.y - mx);
    v0.z = expf(v0.z - mx); v0.w = expf(v0.w - mx);
    v1.x = expf(v1.x - mx); v1.y = expf(v1.y - mx);
    v1.z = expf(v1.z - mx); v1.w = expf(v1.w - mx);
    sp[0] = v0; sp[1] = v1;
    int trg = EI[b * 2 * E_ + E_ + e];
    float* d = g_denom + (b * N_ + trg) * H_;
    red_add_v4(d, v0);
    red_add_v4(d + 4, v1);
}

// -------------------- K5: fused message + rel scatter (warp per edge) ------
__global__ void scatter_kernel(const int* __restrict__ EI,
                               const float* __restrict__ rel) {
    const int b    = blockIdx.y;
    const int lane = threadIdx.x & 31;
    const int e    = blockIdx.x * 8 + (threadIdx.x >> 5);  // grid.x = E/8
    int src = 0, trg = 0;
    if (lane == 0) {
        src = EI[b * 2 * E_ + e];
        trg = EI[b * 2 * E_ + E_ + e];
    }
    src = __shfl_sync(0xFFFFFFFFu, src, 0);
    trg = __shfl_sync(0xFFFFFFFFu, trg, 0);

    float a = 0.f;
    if (lane < 8)
        a = g_se[(size_t)(b * E_ + e) * H_ + lane] /
            (g_denom[(b * N_ + trg) * H_ + lane] + 1e-16f);
    float att0 = __shfl_sync(0xFFFFFFFFu, a, lane >> 3);        // head of col 4*lane
    float att1 = __shfl_sync(0xFFFFFFFFu, a, 4 + (lane >> 3));  // head of col 128+4*lane

    const float4* prow = reinterpret_cast<const float4*>(g_proj + (size_t)(b * N_ + src) * FIN_);
    const float4* rrow = reinterpret_cast<const float4*>(rel    + (size_t)(b * E_ + e) * FIN_);
    float* nrow = g_numer  + (size_t)(b * N_ + trg) * FIN_;
    float* grow = g_relagg + (size_t)(b * N_ + trg) * FIN_;

    float4 p0 = prow[lane], p1 = prow[lane + 32];
    float4 r0 = rrow[lane], r1 = rrow[lane + 32];

    red_add_v4(nrow + 4 * lane,
               make_float4(p0.x * att0, p0.y * att0, p0.z * att0, p0.w * att0));
    red_add_v4(nrow + 128 + 4 * lane,
               make_float4(p1.x * att1, p1.y * att1, p1.z * att1, p1.w * att1));
    red_add_v4(grow + 4 * lane, r0);
    red_add_v4(grow + 128 + 4 * lane, r1);
}

// -------------------- K6: out = elu(relagg @ W^T + numer + x + bias) -------
__global__ void gemm1_kernel(const float* __restrict__ W,
                             const float* __restrict__ x,
                             const float* __restrict__ bias,
                             float* __restrict__ out) {
    __shared__ float As[16][68];
    __shared__ float Bs[16][68];
    const int t  = threadIdx.x;
    const int bm = blockIdx.y * 64;
    const int bn = blockIdx.x * 64;
    const int tx = t & 15, ty = t >> 4;
    const int arow = t >> 2;
    const int kq   = (t & 3) * 4;
    const float* Ap = g_relagg + (bm + arow) * FIN_;
    const float* Wp = W + (bn + arow) * FIN_;
    float acc[4][4] = {};
    for (int k0 = 0; k0 < FIN_; k0 += 16) {
        float4 av = *reinterpret_cast<const float4*>(Ap + k0 + kq);
        float4 bv = *reinterpret_cast<const float4*>(Wp + k0 + kq);
        As[kq+0][arow] = av.x; As[kq+1][arow] = av.y;
        As[kq+2][arow] = av.z; As[kq+3][arow] = av.w;
        Bs[kq+0][arow] = bv.x; Bs[kq+1][arow] = bv.y;
        Bs[kq+2][arow] = bv.z; Bs[kq+3][arow] = bv.w;
        __syncthreads();
        #pragma unroll
        for (int k = 0; k < 16; k++) {
            float4 ar = *reinterpret_cast<const float4*>(&As[k][ty * 4]);
            float4 br = *reinterpret_cast<const float4*>(&Bs[k][tx * 4]);
            acc[0][0] += ar.x * br.x; acc[0][1] += ar.x * br.y;
            acc[0][2] += ar.x * br.z; acc[0][3] += ar.x * br.w;
            acc[1][0] += ar.y * br.x; acc[1][1] += ar.y * br.y;
            acc[1][2] += ar.y * br.z; acc[1][3] += ar.y * br.w;
            acc[2][0] += ar.z * br.x; acc[2][1] += ar.z * br.y;
            acc[2][2] += ar.z * br.z; acc[2][3] += ar.z * br.w;
            acc[3][0] += ar.w * br.x; acc[3][1] += ar.w * br.y;
            acc[3][2] += ar.w * br.z; acc[3][3] += ar.w * br.w;
        }
        __syncthreads();
    }
    const int colb = bn + tx * 4;
    float4 bb = *reinterpret_cast<const float4*>(bias + colb);
    #pragma unroll
    for (int i = 0; i < 4; i++) {
        int row = bm + ty * 4 + i;
        float4 nm = *reinterpret_cast<const float4*>(g_numer + row * FIN_ + colb);
        float4 xv = *reinterpret_cast<const float4*>(x + row * FIN_ + colb);
        float v[4];
        v[0] = acc[i][0] + nm.x + xv.x + bb.x;
        v[1] = acc[i][1] + nm.y + xv.y + bb.y;
        v[2] = acc[i][2] + nm.z + xv.z + bb.z;
        v[3] = acc[i][3] + nm.w + xv.w + bb.w;
        #pragma unroll
        for (int j = 0; j < 4; j++)
            v[j] = (v[j] > 0.f) ? v[j] : (expf(v[j]) - 1.f);
        *reinterpret_cast<float4*>(out + row * FIN_ + colb) =
            make_float4(v[0], v[1], v[2], v[3]);
    }
}

// -------------------- launch ------------------------------------------------
extern "C" void kernel_launch(void* const* d_in, const int* in_sizes, int n_in,
                              void* d_out, int out_size) {
    const float* x     = (const float*)d_in[0];
    const int*   EI    = (const int*)  d_in[1];
    const float* rel   = (const float*)d_in[2];
    const float* W     = (const float*)d_in[3];
    const float* a_src = (const float*)d_in[4];
    const float* a_trg = (const float*)d_in[5];
    const float* bias  = (const float*)d_in[6];
    float* out = (float*)d_out;

    zero_kernel<<<2048, 256>>>();
    gemm0_kernel<<<dim3(FIN_ / 64, (B_ * N_) / 64), 256>>>(x, W);
    s_kernel<<<(B_ * N_ * H_ + 255) / 256, 256>>>(a_src, a_trg);
    edge_score_kernel<<<dim3((E_ + 255) / 256, B_), 256>>>(EI);
    exp_denom_kernel<<<dim3((E_ + 255) / 256, B_), 256>>>(EI);
    scatter_kernel<<<dim3(E_ / 8, B_), 256>>>(EI, rel);
    gemm1_kernel<<<dim3(FIN_ / 64, (B_ * N_) / 64), 256>>>(W, x, bias, out);
}